// round 2
// baseline (speedup 1.0000x reference)
#include <cuda_runtime.h>

// ---------------------------------------------------------------------------
// BGATModel: B=262144 independent tiny graph-attention models.
// One thread per batch element; all weights staged in shared memory.
// ---------------------------------------------------------------------------

namespace {
constexpr int THREADS = 128;
constexpr float D_    = 50.0f;
constexpr float HZ_   = 5.0f;
constexpr float DMIN_ = 0.025f;
constexpr float PMAX_ = 1.0f;
constexpr float SCALE_ = 0.5f;                 // 1/sqrt(HD=4)
constexpr float BMAX_ = 2.0f * 50.0f - 3.0f * 0.025f;  // 99.925

// Shared-memory weight layout (float offsets). Segments padded to 4-float align.
constexpr int WU   = 0;      // (5,8,4,2)  320
constexpr int WA   = 320;    // 320
constexpr int WEo  = 640;    // (5,8,4,1)  160
constexpr int AVo  = 800;    // 160
constexpr int WRES = 960;    // (5,32,2)   320
constexpr int LNUG = 1280;   // 160
constexpr int LNUB = 1440;   // 160
constexpr int LNAG = 1600;   // 160
constexpr int LNAB = 1760;   // 160
constexpr int MUW1 = 1920;   // (5,16,32) 2560
constexpr int MUB1 = 4480;   // 80
constexpr int MUW2 = 4560;   // (5,2,16)  160
constexpr int MUB2 = 4720;   // 10 (pad 12)
constexpr int MAW1 = 4732;   // 2560
constexpr int MAB1 = 7292;   // 80
constexpr int MAW2 = 7372;   // 160
constexpr int MAB2 = 7532;   // 10 (pad 12)
constexpr int RDW1 = 7544;   // (8,4) 32
constexpr int RDB1 = 7576;   // 8
constexpr int RDW2 = 7584;   // (4,8) 32
constexpr int RDB2 = 7616;   // 4
constexpr int RPW1 = 7620;   // 32
constexpr int RPB1 = 7652;   // 8
constexpr int RPW2 = 7660;   // 32
constexpr int RPB2 = 7692;   // 4
constexpr int WTOT = 7696;
}

struct Ptrs { const float* a[28]; };

// LayerNorm over 32 with gain/bias from shared memory.
__device__ __forceinline__ void ln32(const float* __restrict__ v,
                                     const float* __restrict__ g,
                                     const float* __restrict__ bb,
                                     float* __restrict__ h) {
    float s0 = 0.f, s1 = 0.f, s2 = 0.f, s3 = 0.f;
#pragma unroll
    for (int i = 0; i < 32; i += 4) { s0 += v[i]; s1 += v[i+1]; s2 += v[i+2]; s3 += v[i+3]; }
    float mu = (s0 + s1 + s2 + s3) * (1.0f / 32.0f);
    float q0 = 0.f, q1 = 0.f, q2 = 0.f, q3 = 0.f;
#pragma unroll
    for (int i = 0; i < 32; i += 4) {
        float t0 = v[i] - mu, t1 = v[i+1] - mu, t2 = v[i+2] - mu, t3 = v[i+3] - mu;
        q0 = fmaf(t0, t0, q0); q1 = fmaf(t1, t1, q1);
        q2 = fmaf(t2, t2, q2); q3 = fmaf(t3, t3, q3);
    }
    float var = (q0 + q1 + q2 + q3) * (1.0f / 32.0f);
    float r = rsqrtf(var + 1e-5f);
#pragma unroll
    for (int i4 = 0; i4 < 8; i4++) {
        float4 gg = *(const float4*)&g[i4 * 4];
        float4 bv = *(const float4*)&bb[i4 * 4];
        h[i4*4+0] = fmaf((v[i4*4+0] - mu) * r, gg.x, bv.x);
        h[i4*4+1] = fmaf((v[i4*4+1] - mu) * r, gg.y, bv.y);
        h[i4*4+2] = fmaf((v[i4*4+2] - mu) * r, gg.z, bv.z);
        h[i4*4+3] = fmaf((v[i4*4+3] - mu) * r, gg.w, bv.w);
    }
}

// MLP 32 -> 16 (relu) -> 2, weights in shared memory.
__device__ __forceinline__ void mlp2(const float* __restrict__ h,
                                     const float* __restrict__ w1,
                                     const float* __restrict__ b1,
                                     const float* __restrict__ w2,
                                     const float* __restrict__ b2,
                                     float& o0, float& o1) {
    float a0 = 0.f, a1 = 0.f;
    for (int j = 0; j < 16; j++) {
        const float* wr = &w1[j * 32];
        float c0 = b1[j], c1 = 0.f, c2 = 0.f, c3 = 0.f;
#pragma unroll
        for (int i4 = 0; i4 < 8; i4++) {
            float4 w = *(const float4*)&wr[i4 * 4];
            c0 = fmaf(h[i4*4+0], w.x, c0);
            c1 = fmaf(h[i4*4+1], w.y, c1);
            c2 = fmaf(h[i4*4+2], w.z, c2);
            c3 = fmaf(h[i4*4+3], w.w, c3);
        }
        float t = fmaxf((c0 + c1) + (c2 + c3), 0.f);
        a0 = fmaf(t, w2[j],      a0);
        a1 = fmaf(t, w2[16 + j], a1);
    }
    o0 = a0 + b2[0];
    o1 = a1 + b2[1];
}

__global__ __launch_bounds__(THREADS)
void bgat_kernel(Ptrs p, float* __restrict__ out, int B) {
    __shared__ float sW[WTOT];

    // ---- stage all weights into shared memory ----
    {
        const int t = threadIdx.x;
#define CPY(idx, off, sz) \
        for (int i = t; i < (sz); i += THREADS) sW[(off) + i] = p.a[idx][i];
        CPY(3,  WU,   320)  CPY(4,  WA,   320)  CPY(5,  WEo,  160)  CPY(6,  AVo,  160)
        CPY(7,  WRES, 320)  CPY(8,  LNUG, 160)  CPY(9,  LNUB, 160)  CPY(10, LNAG, 160)
        CPY(11, LNAB, 160)  CPY(12, MUW1, 2560) CPY(13, MUB1, 80)   CPY(14, MUW2, 160)
        CPY(15, MUB2, 10)   CPY(16, MAW1, 2560) CPY(17, MAB1, 80)   CPY(18, MAW2, 160)
        CPY(19, MAB2, 10)   CPY(20, RDW1, 32)   CPY(21, RDB1, 8)    CPY(22, RDW2, 32)
        CPY(23, RDB2, 4)    CPY(24, RPW1, 32)   CPY(25, RPB1, 8)    CPY(26, RPW2, 32)
        CPY(27, RPB2, 4)
#undef CPY
    }
    __syncthreads();

    const int b = blockIdx.x * THREADS + threadIdx.x;
    if (b >= B) return;

    // ---- per-element state ----
    float uf[2][2], af[4][2];
    {
        float4 uv = ((const float4*)p.a[0])[b];   // users (B, 2, 2)
        uf[0][0] = uv.x; uf[0][1] = uv.y; uf[1][0] = uv.z; uf[1][1] = uv.w;
        float4 dv = ((const float4*)p.a[1])[b];   // delta_init (B, 4)
        float4 pv = ((const float4*)p.a[2])[b];   // power_init (B, 4)
        af[0][0] = pv.x; af[0][1] = dv.x;
        af[1][0] = pv.y; af[1][1] = dv.y;
        af[2][0] = pv.z; af[2][1] = dv.z;
        af[3][0] = pv.w; af[3][1] = dv.w;
    }

#pragma unroll 1
    for (int d = 0; d < 5; d++) {
        const float* wu_d = &sW[WU  + d * 64];
        const float* wa_d = &sW[WA  + d * 64];
        const float* we_d = &sW[WEo + d * 32];
        const float* av_d = &sW[AVo + d * 32];

        // anchor positions
        float da[4], xpos[4];
        float sd = 1e-6f;
#pragma unroll
        for (int n = 0; n < 4; n++) { da[n] = fmaxf(af[n][1], 0.f); sd += da[n]; }
        float inv_sd = BMAX_ / fmaxf(sd, 1e-6f);
        {
            float cum = 0.f;
#pragma unroll
            for (int n = 0; n < 4; n++) {
                cum += da[n] * inv_sd;
                xpos[n] = cum - D_ + DMIN_ * (float)n;
            }
        }

        float edge[2][4];
#pragma unroll
        for (int m = 0; m < 2; m++)
#pragma unroll
            for (int n = 0; n < 4; n++) {
                float dx = uf[m][0] - xpos[n];
                float dy = uf[m][1];
                edge[m][n] = sqrtf(fmaf(dx, dx, dy * dy));
            }

        float alpha[8][2][4];
        float ucat[2][32];

        // ---- attention: scores, softmax, user aggregation ----
#pragma unroll
        for (int k = 0; k < 8; k++) {
            float4 wu0 = *(const float4*)&wu_d[k * 8];
            float4 wu1 = *(const float4*)&wu_d[k * 8 + 4];
            float4 wa0 = *(const float4*)&wa_d[k * 8];
            float4 wa1 = *(const float4*)&wa_d[k * 8 + 4];
            float4 we4 = *(const float4*)&we_d[k * 4];
            float4 av4 = *(const float4*)&av_d[k * 4];
            float wuh[4][2] = {{wu0.x,wu0.y},{wu0.z,wu0.w},{wu1.x,wu1.y},{wu1.z,wu1.w}};
            float wah[4][2] = {{wa0.x,wa0.y},{wa0.z,wa0.w},{wa1.x,wa1.y},{wa1.z,wa1.w}};
            float weh[4] = {we4.x, we4.y, we4.z, we4.w};
            float avh[4] = {av4.x, av4.y, av4.z, av4.w};

            float U[2][4], A[4][4];
#pragma unroll
            for (int h = 0; h < 4; h++) {
#pragma unroll
                for (int m = 0; m < 2; m++)
                    U[m][h] = fmaf(uf[m][0], wuh[h][0], uf[m][1] * wuh[h][1]);
#pragma unroll
                for (int n = 0; n < 4; n++)
                    A[n][h] = fmaf(af[n][0], wah[h][0], af[n][1] * wah[h][1]);
            }

#pragma unroll
            for (int m = 0; m < 2; m++) {
                float sc[4];
#pragma unroll
                for (int n = 0; n < 4; n++) {
                    float e = edge[m][n];
                    float acc = 0.f;
#pragma unroll
                    for (int h = 0; h < 4; h++) {
                        float s = U[m][h] + A[n][h] + e * weh[h];
                        s = (s > 0.f) ? s : 0.2f * s;          // leaky_relu 0.2
                        acc = fmaf(s, avh[h], acc);
                    }
                    sc[n] = acc * SCALE_;
                }
                float mx = fmaxf(fmaxf(sc[0], sc[1]), fmaxf(sc[2], sc[3]));
                float ssum = 0.f;
#pragma unroll
                for (int n = 0; n < 4; n++) { sc[n] = __expf(sc[n] - mx); ssum += sc[n]; }
                float rs = __fdividef(1.0f, ssum);
#pragma unroll
                for (int n = 0; n < 4; n++) alpha[k][m][n] = sc[n] * rs;
            }

            // ucat[m][k*4+h] = sum_n (A[n][h] + E[m][n][h]) * alpha[k][m][n]
#pragma unroll
            for (int m = 0; m < 2; m++)
#pragma unroll
                for (int h = 0; h < 4; h++) {
                    float acc = 0.f;
#pragma unroll
                    for (int n = 0; n < 4; n++)
                        acc = fmaf(A[n][h] + edge[m][n] * weh[h], alpha[k][m][n], acc);
                    ucat[m][k * 4 + h] = acc;
                }
        }

        // residual Wres:  ucat[m][j] += uf[m] . Wres[d][j]
        {
            const float* wres_d = &sW[WRES + d * 64];
#pragma unroll
            for (int j2 = 0; j2 < 16; j2++) {
                float4 w = *(const float4*)&wres_d[j2 * 4];
#pragma unroll
                for (int m = 0; m < 2; m++) {
                    ucat[m][2*j2]   = fmaf(uf[m][0], w.x, fmaf(uf[m][1], w.y, ucat[m][2*j2]));
                    ucat[m][2*j2+1] = fmaf(uf[m][0], w.z, fmaf(uf[m][1], w.w, ucat[m][2*j2+1]));
                }
            }
        }

        // ---- user branch: LN + MLP -> new uf (keep old uf until agent pass done)
        float ufn[2][2];
#pragma unroll
        for (int m = 0; m < 2; m++) {
            float hbuf[32];
            ln32(ucat[m], &sW[LNUG + d * 32], &sW[LNUB + d * 32], hbuf);
            mlp2(hbuf, &sW[MUW1 + d * 512], &sW[MUB1 + d * 16],
                 &sW[MUW2 + d * 32], &sW[MUB2 + d * 2], ufn[m][0], ufn[m][1]);
        }

        // ---- agent branch: recompute U,E; aggregate, LN + MLP -> new af
        float afn[4][2];
#pragma unroll
        for (int n = 0; n < 4; n++) {
            float vec[32];
#pragma unroll
            for (int k = 0; k < 8; k++) {
                float4 wu0 = *(const float4*)&wu_d[k * 8];
                float4 wu1 = *(const float4*)&wu_d[k * 8 + 4];
                float4 we4 = *(const float4*)&we_d[k * 4];
                float wuh[4][2] = {{wu0.x,wu0.y},{wu0.z,wu0.w},{wu1.x,wu1.y},{wu1.z,wu1.w}};
                float weh[4] = {we4.x, we4.y, we4.z, we4.w};
                float a0 = alpha[k][0][n];
                float a1 = alpha[k][1][n];
                float e0 = edge[0][n];
                float e1 = edge[1][n];
#pragma unroll
                for (int h = 0; h < 4; h++) {
                    float U0 = fmaf(uf[0][0], wuh[h][0], uf[0][1] * wuh[h][1]);
                    float U1 = fmaf(uf[1][0], wuh[h][0], uf[1][1] * wuh[h][1]);
                    vec[k * 4 + h] = fmaf(U0 + e0 * weh[h], a0, (U1 + e1 * weh[h]) * a1);
                }
            }
            float hbuf[32];
            ln32(vec, &sW[LNAG + d * 32], &sW[LNAB + d * 32], hbuf);
            mlp2(hbuf, &sW[MAW1 + d * 512], &sW[MAB1 + d * 16],
                 &sW[MAW2 + d * 32], &sW[MAB2 + d * 2], afn[n][0], afn[n][1]);
        }

#pragma unroll
        for (int m = 0; m < 2; m++) { uf[m][0] = ufn[m][0]; uf[m][1] = ufn[m][1]; }
#pragma unroll
        for (int n = 0; n < 4; n++) { af[n][0] = afn[n][0]; af[n][1] = afn[n][1]; }
    }

    // ---- readout heads ----
    // delta head
    float td[8];
#pragma unroll
    for (int i = 0; i < 8; i++) {
        float acc = sW[RDB1 + i];
#pragma unroll
        for (int n = 0; n < 4; n++) acc = fmaf(af[n][1], sW[RDW1 + i * 4 + n], acc);
        td[i] = fmaxf(acc, 0.f);
    }
    float daux[4], sumd = 0.f;
#pragma unroll
    for (int j = 0; j < 4; j++) {
        float acc = sW[RDB2 + j];
#pragma unroll
        for (int i = 0; i < 8; i++) acc = fmaf(td[i], sW[RDW2 + j * 8 + i], acc);
        daux[j] = fmaxf(acc, 0.001f);
        sumd += daux[j];
    }
    float fd = BMAX_ / sumd;
    float sdelta[4], x[4];
    {
        float cum = 0.f;
#pragma unroll
        for (int n = 0; n < 4; n++) {
            sdelta[n] = daux[n] * fd;
            cum += sdelta[n];
            x[n] = cum + DMIN_ * (float)n - D_ * (float)(n + 1);
        }
    }

    // power head
    float tp[8];
#pragma unroll
    for (int i = 0; i < 8; i++) {
        float acc = sW[RPB1 + i];
#pragma unroll
        for (int n = 0; n < 4; n++) acc = fmaf(af[n][0], sW[RPW1 + i * 4 + n], acc);
        tp[i] = fmaxf(acc, 0.f);
    }
    float paux[4], sump = 1e-6f;
#pragma unroll
    for (int j = 0; j < 4; j++) {
        float acc = sW[RPB2 + j];
#pragma unroll
        for (int i = 0; i < 8; i++) acc = fmaf(tp[i], sW[RPW2 + j * 8 + i], acc);
        paux[j] = fmaxf(acc, 0.001f);
        sump += paux[j];
    }
    float fp = PMAX_ / fmaxf(PMAX_, sump);

    // ---- outputs: [scaled_power (B,4) | scaled_delta (B,4) | final_positions (B,4,3)]
    float4 pw = make_float4(paux[0] * fp, paux[1] * fp, paux[2] * fp, paux[3] * fp);
    ((float4*)out)[b] = pw;
    ((float4*)(out + 4 * (size_t)B))[b] = make_float4(sdelta[0], sdelta[1], sdelta[2], sdelta[3]);
    float* op = out + 8 * (size_t)B + (size_t)b * 12;
    ((float4*)op)[0] = make_float4(x[0], 0.f, HZ_, x[1]);
    ((float4*)op)[1] = make_float4(0.f, HZ_, x[2], 0.f);
    ((float4*)op)[2] = make_float4(HZ_, x[3], 0.f, HZ_);
}

extern "C" void kernel_launch(void* const* d_in, const int* in_sizes, int n_in,
                              void* d_out, int out_size) {
    Ptrs p;
    for (int i = 0; i < 28; i++) p.a[i] = (const float*)d_in[i];
    int B = in_sizes[0] / 4;   // users is (B, 2, 2)
    int grid = (B + THREADS - 1) / THREADS;
    bgat_kernel<<<grid, THREADS>>>(p, (float*)d_out, B);
}

// round 3
// speedup vs baseline: 1.3803x; 1.3803x over previous
#include <cuda_runtime.h>

// ---------------------------------------------------------------------------
// BGATModel: B=262144 independent tiny graph-attention models.
// One thread per element. LN+MLP-layer1 fused into the attention k-loop via
// precomputed (w1*g) weights; heavy use of packed fma.rn.f32x2.
// ---------------------------------------------------------------------------

namespace {
constexpr int THREADS = 64;
constexpr float D_    = 50.0f;
constexpr float HZ_   = 5.0f;
constexpr float DMIN_ = 0.025f;
constexpr float PMAX_ = 1.0f;
constexpr float SCALE_ = 0.5f;                       // 1/sqrt(HD=4)
constexpr float BMAX_ = 2.0f * 50.0f - 3.0f * 0.025f; // 99.925

// shared float offsets
constexpr int CWU = 0;     // [d][k][c][h]     320
constexpr int CWA = 320;   //                  320
constexpr int CWE = 640;   // [d][k][h]        160
constexpr int CAV = 800;   //                  160
constexpr int WRT = 960;   // [d][c][i]        320  (Wres transposed)
constexpr int WPU = 1280;  // [d][i][j] (w1*g)^T user  2560
constexpr int WPA = 3840;  //                  agent   2560
constexpr int SUN = 6400;  // [d][j] -sum_i w1g   80
constexpr int BUC = 6480;  // [d][j] b1+w1@lnb    80
constexpr int SAN = 6560;  constexpr int BAC = 6640;
constexpr int W2U = 6720;  // [d][j][2] packed (w2[0][j],w2[1][j]) 160
constexpr int W2A = 6880;
constexpr int B2U = 7040;  // [d][2] 10 (pad)
constexpr int B2A = 7052;  // 10 (pad)
constexpr int RDW1 = 7064, RDB1 = 7096, RDW2 = 7104, RDB2 = 7136;
constexpr int RPW1 = 7140, RPB1 = 7172, RPW2 = 7180, RPB2 = 7212;
constexpr int WTOT = 7216;
}

typedef unsigned long long ull;
struct Ptrs { const float* a[28]; };

__device__ __forceinline__ ull pk2(float lo, float hi) {
    ull r; asm("mov.b64 %0,{%1,%2};" : "=l"(r) : "f"(lo), "f"(hi)); return r;
}
__device__ __forceinline__ void upk2(ull v, float& lo, float& hi) {
    asm("mov.b64 {%0,%1},%2;" : "=f"(lo), "=f"(hi) : "l"(v));
}
__device__ __forceinline__ ull dupf(float x) { return pk2(x, x); }
__device__ __forceinline__ ull f2fma(ull a, ull b, ull c) {
    ull r; asm("fma.rn.f32x2 %0,%1,%2,%3;" : "=l"(r) : "l"(a), "l"(b), "l"(c)); return r;
}
__device__ __forceinline__ ull f2mul(ull a, ull b) {
    ull r; asm("mul.rn.f32x2 %0,%1,%2;" : "=l"(r) : "l"(a), "l"(b)); return r;
}
__device__ __forceinline__ ull f2add(ull a, ull b) {
    ull r; asm("add.rn.f32x2 %0,%1,%2;" : "=l"(r) : "l"(a), "l"(b)); return r;
}

__global__ __launch_bounds__(THREADS, 5)
void bgat_kernel(Ptrs p, float* __restrict__ out, int B) {
    __shared__ float sW[WTOT];

    // ---------------- staging + weight precompute ----------------
    {
        const int t = threadIdx.x;
        for (int x = t; x < 320; x += THREADS) {                // Wu, Wa -> [d][k][c][h]
            int d = x >> 6, k = (x >> 3) & 7, h = (x >> 1) & 3, c = x & 1;
            sW[CWU + (d * 8 + k) * 8 + c * 4 + h] = p.a[3][x];
            sW[CWA + (d * 8 + k) * 8 + c * 4 + h] = p.a[4][x];
        }
        for (int x = t; x < 160; x += THREADS) { sW[CWE + x] = p.a[5][x]; sW[CAV + x] = p.a[6][x]; }
        for (int x = t; x < 320; x += THREADS) {                // Wres transpose
            int d = x >> 6, i = (x >> 1) & 31, c = x & 1;
            sW[WRT + (d * 2 + c) * 32 + i] = p.a[7][x];
        }
        for (int x = t; x < 2560; x += THREADS) {               // (w1 * g)^T
            int d = x >> 9, j = (x >> 5) & 15, i = x & 31;
            sW[WPU + (d * 32 + i) * 16 + j] = p.a[12][x] * p.a[8][d * 32 + i];
            sW[WPA + (d * 32 + i) * 16 + j] = p.a[16][x] * p.a[10][d * 32 + i];
        }
        for (int x = t; x < 80; x += THREADS) {                 // -S, B
            int d = x >> 4, j = x & 15;
            float su = 0.f, bu = 0.f, sa = 0.f, ba = 0.f;
            for (int i = 0; i < 32; i++) {
                float wu_ = p.a[12][(d * 16 + j) * 32 + i];
                float wa_ = p.a[16][(d * 16 + j) * 32 + i];
                su += wu_ * p.a[8][d * 32 + i];  bu += wu_ * p.a[9][d * 32 + i];
                sa += wa_ * p.a[10][d * 32 + i]; ba += wa_ * p.a[11][d * 32 + i];
            }
            sW[SUN + x] = -su; sW[BUC + x] = p.a[13][x] + bu;
            sW[SAN + x] = -sa; sW[BAC + x] = p.a[17][x] + ba;
        }
        for (int x = t; x < 160; x += THREADS) {                // w2 packed pairs
            int d = x >> 5, j = (x >> 1) & 15, c = x & 1;
            sW[W2U + d * 32 + j * 2 + c] = p.a[14][(d * 2 + c) * 16 + j];
            sW[W2A + d * 32 + j * 2 + c] = p.a[18][(d * 2 + c) * 16 + j];
        }
        for (int x = t; x < 10; x += THREADS) {
            int d = x >> 1, c = x & 1;
            sW[B2U + d * 2 + c] = p.a[15][x];
            sW[B2A + d * 2 + c] = p.a[19][x];
        }
        for (int x = t; x < 32; x += THREADS) {
            sW[RDW1 + x] = p.a[20][x]; sW[RDW2 + x] = p.a[22][x];
            sW[RPW1 + x] = p.a[24][x]; sW[RPW2 + x] = p.a[26][x];
        }
        for (int x = t; x < 8; x += THREADS) { sW[RDB1 + x] = p.a[21][x]; sW[RPB1 + x] = p.a[25][x]; }
        for (int x = t; x < 4; x += THREADS) { sW[RDB2 + x] = p.a[23][x]; sW[RPB2 + x] = p.a[27][x]; }
    }
    __syncthreads();

    const int b = blockIdx.x * THREADS + threadIdx.x;
    if (b >= B) return;

    float uf[2][2], af[4][2];
    {
        float4 uv = ((const float4*)p.a[0])[b];
        uf[0][0] = uv.x; uf[0][1] = uv.y; uf[1][0] = uv.z; uf[1][1] = uv.w;
        float4 dv = ((const float4*)p.a[1])[b];
        float4 pv = ((const float4*)p.a[2])[b];
        af[0][0] = pv.x; af[0][1] = dv.x; af[1][0] = pv.y; af[1][1] = dv.y;
        af[2][0] = pv.z; af[2][1] = dv.z; af[3][0] = pv.w; af[3][1] = dv.w;
    }

#pragma unroll 1
    for (int d = 0; d < 5; d++) {
        // anchor positions + edges
        float da[4], xpos[4], sd = 1e-6f;
#pragma unroll
        for (int n = 0; n < 4; n++) { da[n] = fmaxf(af[n][1], 0.f); sd += da[n]; }
        float inv_sd = BMAX_ / fmaxf(sd, 1e-6f);
        { float cum = 0.f;
#pragma unroll
          for (int n = 0; n < 4; n++) { cum += da[n] * inv_sd; xpos[n] = cum - D_ + DMIN_ * (float)n; } }

        ull dedg[2][4];
#pragma unroll
        for (int m = 0; m < 2; m++)
#pragma unroll
            for (int n = 0; n < 4; n++) {
                float dx = uf[m][0] - xpos[n], dy = uf[m][1];
                dedg[m][n] = dupf(sqrtf(fmaf(dx, dx, dy * dy)));
            }

        ull duf0[2], duf1[2], daf0[4], daf1[4];
#pragma unroll
        for (int m = 0; m < 2; m++) { duf0[m] = dupf(uf[m][0]); duf1[m] = dupf(uf[m][1]); }
#pragma unroll
        for (int n = 0; n < 4; n++) { daf0[n] = dupf(af[n][0]); daf1[n] = dupf(af[n][1]); }

        // fused LN/MLP1 accumulators (packed over j-pairs / h-pairs)
        ull uacc[2][8], aacc[4][8];
        ull usum[2], usq[2], asum[4], asq[4];
#pragma unroll
        for (int m = 0; m < 2; m++) {
            usum[m] = 0ull; usq[m] = 0ull;
#pragma unroll
            for (int j = 0; j < 8; j++) uacc[m][j] = 0ull;
        }
#pragma unroll
        for (int n = 0; n < 4; n++) {
            asum[n] = 0ull; asq[n] = 0ull;
#pragma unroll
            for (int j = 0; j < 8; j++) aacc[n][j] = 0ull;
        }

#pragma unroll 2
        for (int k = 0; k < 8; k++) {
            const ull* wu2 = (const ull*)&sW[CWU + (d * 8 + k) * 8];
            const ull* wa2 = (const ull*)&sW[CWA + (d * 8 + k) * 8];
            const ull* we2 = (const ull*)&sW[CWE + (d * 8 + k) * 4];
            const float* avk = &sW[CAV + (d * 8 + k) * 4];

            ull U2[2][2], A2[4][2];
#pragma unroll
            for (int m = 0; m < 2; m++) {
                U2[m][0] = f2fma(duf0[m], wu2[0], f2mul(duf1[m], wu2[2]));
                U2[m][1] = f2fma(duf0[m], wu2[1], f2mul(duf1[m], wu2[3]));
            }
#pragma unroll
            for (int n = 0; n < 4; n++) {
                A2[n][0] = f2fma(daf0[n], wa2[0], f2mul(daf1[n], wa2[2]));
                A2[n][1] = f2fma(daf0[n], wa2[1], f2mul(daf1[n], wa2[3]));
            }

            float av0 = avk[0], av1 = avk[1], av2v = avk[2], av3 = avk[3];
            float alpha[2][4];
#pragma unroll
            for (int m = 0; m < 2; m++) {
                float sc[4];
#pragma unroll
                for (int n = 0; n < 4; n++) {
                    ull e0 = f2mul(dedg[m][n], we2[0]);
                    ull e1 = f2mul(dedg[m][n], we2[1]);
                    ull s0 = f2add(f2add(U2[m][0], A2[n][0]), e0);
                    ull s1 = f2add(f2add(U2[m][1], A2[n][1]), e1);
                    float x0, x1, x2, x3;
                    upk2(s0, x0, x1); upk2(s1, x2, x3);
                    x0 = (x0 > 0.f) ? x0 : 0.2f * x0;
                    x1 = (x1 > 0.f) ? x1 : 0.2f * x1;
                    x2 = (x2 > 0.f) ? x2 : 0.2f * x2;
                    x3 = (x3 > 0.f) ? x3 : 0.2f * x3;
                    sc[n] = fmaf(x0, av0, fmaf(x1, av1, fmaf(x2, av2v, x3 * av3))) * SCALE_;
                }
                float mx = fmaxf(fmaxf(sc[0], sc[1]), fmaxf(sc[2], sc[3]));
                float ssum = 0.f;
#pragma unroll
                for (int n = 0; n < 4; n++) { sc[n] = __expf(sc[n] - mx); ssum += sc[n]; }
                float rs = __fdividef(1.0f, ssum);
#pragma unroll
                for (int n = 0; n < 4; n++) alpha[m][n] = sc[n] * rs;
            }
            ull dal[2][4];
#pragma unroll
            for (int m = 0; m < 2; m++)
#pragma unroll
                for (int n = 0; n < 4; n++) dal[m][n] = dupf(alpha[m][n]);

#pragma unroll
            for (int pp = 0; pp < 2; pp++) {
                ull wres0 = *(const ull*)&sW[WRT + (d * 2 + 0) * 32 + k * 4 + pp * 2];
                ull wres1 = *(const ull*)&sW[WRT + (d * 2 + 1) * 32 + k * 4 + pp * 2];
                ull u2[2], v2[4];
#pragma unroll
                for (int m = 0; m < 2; m++)
                    u2[m] = f2fma(duf0[m], wres0, f2mul(duf1[m], wres1));
#pragma unroll
                for (int n = 0; n < 4; n++) {
                    ull e0 = f2mul(dedg[0][n], we2[pp]);
                    u2[0] = f2fma(f2add(A2[n][pp], e0), dal[0][n], u2[0]);
                    ull ue0 = f2add(U2[0][pp], e0);
                    ull e1 = f2mul(dedg[1][n], we2[pp]);
                    u2[1] = f2fma(f2add(A2[n][pp], e1), dal[1][n], u2[1]);
                    ull ue1 = f2add(U2[1][pp], e1);
                    v2[n] = f2fma(ue1, dal[1][n], f2mul(ue0, dal[0][n]));
                }
#pragma unroll
                for (int m = 0; m < 2; m++) {
                    usum[m] = f2add(usum[m], u2[m]);
                    usq[m]  = f2fma(u2[m], u2[m], usq[m]);
                }
#pragma unroll
                for (int n = 0; n < 4; n++) {
                    asum[n] = f2add(asum[n], v2[n]);
                    asq[n]  = f2fma(v2[n], v2[n], asq[n]);
                }
                float ul[2][2], vl[4][2];
#pragma unroll
                for (int m = 0; m < 2; m++) upk2(u2[m], ul[m][0], ul[m][1]);
#pragma unroll
                for (int n = 0; n < 4; n++) upk2(v2[n], vl[n][0], vl[n][1]);

#pragma unroll
                for (int ln = 0; ln < 2; ln++) {
                    const int i = k * 4 + pp * 2 + ln;
                    const ulonglong2* ru = (const ulonglong2*)&sW[WPU + (d * 32 + i) * 16];
                    ulonglong2 r0 = ru[0], r1 = ru[1], r2 = ru[2], r3 = ru[3];
#pragma unroll
                    for (int m = 0; m < 2; m++) {
                        ull du = dupf(ul[m][ln]);
                        uacc[m][0] = f2fma(du, r0.x, uacc[m][0]);
                        uacc[m][1] = f2fma(du, r0.y, uacc[m][1]);
                        uacc[m][2] = f2fma(du, r1.x, uacc[m][2]);
                        uacc[m][3] = f2fma(du, r1.y, uacc[m][3]);
                        uacc[m][4] = f2fma(du, r2.x, uacc[m][4]);
                        uacc[m][5] = f2fma(du, r2.y, uacc[m][5]);
                        uacc[m][6] = f2fma(du, r3.x, uacc[m][6]);
                        uacc[m][7] = f2fma(du, r3.y, uacc[m][7]);
                    }
                    const ulonglong2* ra = (const ulonglong2*)&sW[WPA + (d * 32 + i) * 16];
                    ulonglong2 q0 = ra[0], q1 = ra[1], q2 = ra[2], q3 = ra[3];
#pragma unroll
                    for (int n = 0; n < 4; n++) {
                        ull dv = dupf(vl[n][ln]);
                        aacc[n][0] = f2fma(dv, q0.x, aacc[n][0]);
                        aacc[n][1] = f2fma(dv, q0.y, aacc[n][1]);
                        aacc[n][2] = f2fma(dv, q1.x, aacc[n][2]);
                        aacc[n][3] = f2fma(dv, q1.y, aacc[n][3]);
                        aacc[n][4] = f2fma(dv, q2.x, aacc[n][4]);
                        aacc[n][5] = f2fma(dv, q2.y, aacc[n][5]);
                        aacc[n][6] = f2fma(dv, q3.x, aacc[n][6]);
                        aacc[n][7] = f2fma(dv, q3.y, aacc[n][7]);
                    }
                }
            }
        }

        // -------- epilogue: finish LN + MLP per branch instance --------
        float ufn[2][2], afn[4][2];
        {
            const ull* sn = (const ull*)&sW[SUN + d * 16];
            const ull* bc = (const ull*)&sW[BUC + d * 16];
            const ull* w2 = (const ull*)&sW[W2U + d * 32];
            ull b2 = *(const ull*)&sW[B2U + d * 2];
#pragma unroll
            for (int m = 0; m < 2; m++) {
                float s0, s1, q0, q1;
                upk2(usum[m], s0, s1); upk2(usq[m], q0, q1);
                float mu = (s0 + s1) * (1.0f / 32.0f);
                float var = (q0 + q1) * (1.0f / 32.0f) - mu * mu;
                float rr = rsqrtf(var + 1e-5f);
                ull dmu = dupf(mu), drr = dupf(rr);
                ull o2 = b2;
#pragma unroll
                for (int jp = 0; jp < 8; jp++) {
                    ull t2 = f2fma(dmu, sn[jp], uacc[m][jp]);
                    ull c2 = f2fma(drr, t2, bc[jp]);
                    float c0, c1; upk2(c2, c0, c1);
                    c0 = fmaxf(c0, 0.f); c1 = fmaxf(c1, 0.f);
                    o2 = f2fma(dupf(c0), w2[2 * jp], o2);
                    o2 = f2fma(dupf(c1), w2[2 * jp + 1], o2);
                }
                upk2(o2, ufn[m][0], ufn[m][1]);
            }
        }
        {
            const ull* sn = (const ull*)&sW[SAN + d * 16];
            const ull* bc = (const ull*)&sW[BAC + d * 16];
            const ull* w2 = (const ull*)&sW[W2A + d * 32];
            ull b2 = *(const ull*)&sW[B2A + d * 2];
#pragma unroll
            for (int n = 0; n < 4; n++) {
                float s0, s1, q0, q1;
                upk2(asum[n], s0, s1); upk2(asq[n], q0, q1);
                float mu = (s0 + s1) * (1.0f / 32.0f);
                float var = (q0 + q1) * (1.0f / 32.0f) - mu * mu;
                float rr = rsqrtf(var + 1e-5f);
                ull dmu = dupf(mu), drr = dupf(rr);
                ull o2 = b2;
#pragma unroll
                for (int jp = 0; jp < 8; jp++) {
                    ull t2 = f2fma(dmu, sn[jp], aacc[n][jp]);
                    ull c2 = f2fma(drr, t2, bc[jp]);
                    float c0, c1; upk2(c2, c0, c1);
                    c0 = fmaxf(c0, 0.f); c1 = fmaxf(c1, 0.f);
                    o2 = f2fma(dupf(c0), w2[2 * jp], o2);
                    o2 = f2fma(dupf(c1), w2[2 * jp + 1], o2);
                }
                upk2(o2, afn[n][0], afn[n][1]);
            }
        }
#pragma unroll
        for (int m = 0; m < 2; m++) { uf[m][0] = ufn[m][0]; uf[m][1] = ufn[m][1]; }
#pragma unroll
        for (int n = 0; n < 4; n++) { af[n][0] = afn[n][0]; af[n][1] = afn[n][1]; }
    }

    // ---------------- readout heads ----------------
    float td[8];
#pragma unroll
    for (int i = 0; i < 8; i++) {
        float acc = sW[RDB1 + i];
#pragma unroll
        for (int n = 0; n < 4; n++) acc = fmaf(af[n][1], sW[RDW1 + i * 4 + n], acc);
        td[i] = fmaxf(acc, 0.f);
    }
    float daux[4], sumd = 0.f;
#pragma unroll
    for (int j = 0; j < 4; j++) {
        float acc = sW[RDB2 + j];
#pragma unroll
        for (int i = 0; i < 8; i++) acc = fmaf(td[i], sW[RDW2 + j * 8 + i], acc);
        daux[j] = fmaxf(acc, 0.001f);
        sumd += daux[j];
    }
    float fd = BMAX_ / sumd;
    float sdelta[4], x[4];
    { float cum = 0.f;
#pragma unroll
      for (int n = 0; n < 4; n++) {
          sdelta[n] = daux[n] * fd;
          cum += sdelta[n];
          x[n] = cum + DMIN_ * (float)n - D_ * (float)(n + 1);
      } }

    float tp[8];
#pragma unroll
    for (int i = 0; i < 8; i++) {
        float acc = sW[RPB1 + i];
#pragma unroll
        for (int n = 0; n < 4; n++) acc = fmaf(af[n][0], sW[RPW1 + i * 4 + n], acc);
        tp[i] = fmaxf(acc, 0.f);
    }
    float paux[4], sump = 1e-6f;
#pragma unroll
    for (int j = 0; j < 4; j++) {
        float acc = sW[RPB2 + j];
#pragma unroll
        for (int i = 0; i < 8; i++) acc = fmaf(tp[i], sW[RPW2 + j * 8 + i], acc);
        paux[j] = fmaxf(acc, 0.001f);
        sump += paux[j];
    }
    float fp = PMAX_ / fmaxf(PMAX_, sump);

    ((float4*)out)[b] = make_float4(paux[0] * fp, paux[1] * fp, paux[2] * fp, paux[3] * fp);
    ((float4*)(out + 4 * (size_t)B))[b] = make_float4(sdelta[0], sdelta[1], sdelta[2], sdelta[3]);
    float* op = out + 8 * (size_t)B + (size_t)b * 12;
    ((float4*)op)[0] = make_float4(x[0], 0.f, HZ_, x[1]);
    ((float4*)op)[1] = make_float4(0.f, HZ_, x[2], 0.f);
    ((float4*)op)[2] = make_float4(HZ_, x[3], 0.f, HZ_);
}

extern "C" void kernel_launch(void* const* d_in, const int* in_sizes, int n_in,
                              void* d_out, int out_size) {
    Ptrs p;
    for (int i = 0; i < 28; i++) p.a[i] = (const float*)d_in[i];
    int B = in_sizes[0] / 4;
    int grid = (B + THREADS - 1) / THREADS;
    bgat_kernel<<<grid, THREADS>>>(p, (float*)d_out, B);
}